// round 14
// baseline (speedup 1.0000x reference)
#include <cuda_runtime.h>
#include <cuda_fp16.h>
#include <cstdint>

#define T_TOK 8192
#define HID   2048
#define NEXP  8
#define INTERD 2816
#define GUD   (2*INTERD)      // 5632
#define NSLOT (T_TOK*2)       // 16384

#define BM 128
#define BN1 64
#define BN2 128
#define BK 32                  // halfs per K-chunk (64 B rows)
#define SPADH 40               // halfs per smem row (80 B, 16B-aligned)
#define STAGES 3
#define STAGE_H (256*SPADH)    // A(128 rows) + B(128 rows) halfs per stage
#define SMEM_BYTES (STAGES*STAGE_H*2)   // 61440 B

// ---------------- scratch (static device globals; no allocation) -------------
__device__ int    g_counts[NEXP];
__device__ int    g_offsets[NEXP];
__device__ int    g_fill[NEXP];
__device__ int    g_tk_e[NSLOT];
__device__ float  g_tk_w[NSLOT];
__device__ int    g_slot_token[NSLOT];
__device__ int    g_token_slot[NSLOT];
__device__ __half g_xh  [(size_t)T_TOK * HID];         // fp16 x (34 MB)
__device__ __half g_wguh[(size_t)NEXP * GUD * HID];    // fp16 w_gate_up (185 MB)
__device__ __half g_wdnh[(size_t)NEXP * HID * INTERD]; // fp16 w_down (92 MB)
__device__ __half g_interh[(size_t)NSLOT * INTERD];    // fp16 activations (92 MB)
__device__ __half g_south[(size_t)NSLOT * HID];        // fp16 down output (67 MB)

// ---------------- helpers ----------------------------------------------------
__device__ __forceinline__ uint32_t uldh(const __half* p) {
    return *(const uint32_t*)p;
}
__device__ __forceinline__ void mma_f16(float c[4], const uint32_t a[4], const uint32_t b[2]) {
    asm volatile(
        "mma.sync.aligned.m16n8k16.row.col.f32.f16.f16.f32 "
        "{%0,%1,%2,%3}, {%4,%5,%6,%7}, {%8,%9}, {%0,%1,%2,%3};\n"
        : "+f"(c[0]), "+f"(c[1]), "+f"(c[2]), "+f"(c[3])
        : "r"(a[0]), "r"(a[1]), "r"(a[2]), "r"(a[3]), "r"(b[0]), "r"(b[1]));
}
__device__ __forceinline__ uint32_t sptr(const void* p) {
    return (uint32_t)__cvta_generic_to_shared(p);
}
__device__ __forceinline__ void cp16(uint32_t dst, const void* src, int sz) {
    asm volatile("cp.async.cg.shared.global [%0], [%1], 16, %2;\n"
                 :: "r"(dst), "l"(src), "r"(sz));
}
__device__ __forceinline__ void cp_commit() {
    asm volatile("cp.async.commit_group;\n");
}
__device__ __forceinline__ void cp_wait1() {
    asm volatile("cp.async.wait_group 1;\n");
}

// ---------------- kernel 0: zero counters ------------------------------------
__global__ void zero_kernel() {
    int i = threadIdx.x;
    if (i < NEXP) { g_counts[i] = 0; g_fill[i] = 0; }
}

// ---------------- convert: fp32 -> fp16 (weights, one-time) -------------------
__global__ __launch_bounds__(256)
void tohalf_kernel(const float4* __restrict__ in, uint2* __restrict__ out, int n4) {
    int stride = gridDim.x * blockDim.x;
    for (int i = blockIdx.x * blockDim.x + threadIdx.x; i < n4; i += stride) {
        float4 v = in[i];
        __half2 h01 = __floats2half2_rn(v.x, v.y);
        __half2 h23 = __floats2half2_rn(v.z, v.w);
        uint2 o;
        o.x = *(uint32_t*)&h01;
        o.y = *(uint32_t*)&h23;
        out[i] = o;
    }
}

// ---------------- kernel 1: router (fp32, exact) + x->fp16 fuse ---------------
__global__ __launch_bounds__(128)
void router_kernel(const float* __restrict__ x, const float* __restrict__ gw,
                   const float* __restrict__ gb, const float* __restrict__ ebias) {
    const int t = blockIdx.x;
    const float* xr = x + (size_t)t * HID;
    __half* xhr = g_xh + (size_t)t * HID;
    float acc[NEXP];
    #pragma unroll
    for (int e = 0; e < NEXP; e++) acc[e] = 0.f;

    for (int h = threadIdx.x; h < HID; h += 128) {
        float xv = xr[h];
        xhr[h] = __float2half_rn(xv);          // fused fp16 conversion
        #pragma unroll
        for (int e = 0; e < NEXP; e++) acc[e] += xv * gw[e * HID + h];
    }
    #pragma unroll
    for (int off = 16; off > 0; off >>= 1) {
        #pragma unroll
        for (int e = 0; e < NEXP; e++)
            acc[e] += __shfl_down_sync(0xffffffffu, acc[e], off);
    }
    __shared__ float ws[4][NEXP];
    int warp = threadIdx.x >> 5, lane = threadIdx.x & 31;
    if (lane == 0) {
        #pragma unroll
        for (int e = 0; e < NEXP; e++) ws[warp][e] = acc[e];
    }
    __syncthreads();
    if (threadIdx.x == 0) {
        float lg[NEXP];
        #pragma unroll
        for (int e = 0; e < NEXP; e++)
            lg[e] = ws[0][e] + ws[1][e] + ws[2][e] + ws[3][e] + gb[e];
        float m = lg[0];
        #pragma unroll
        for (int e = 1; e < NEXP; e++) m = fmaxf(m, lg[e]);
        float p[NEXP], s = 0.f;
        #pragma unroll
        for (int e = 0; e < NEXP; e++) { p[e] = expf(lg[e] - m); s += p[e]; }
        float r[NEXP];
        #pragma unroll
        for (int e = 0; e < NEXP; e++) r[e] = p[e] / s + ebias[e];
        int i0 = 0;
        #pragma unroll
        for (int e = 1; e < NEXP; e++) if (r[e] > r[i0]) i0 = e;
        int i1 = (i0 == 0) ? 1 : 0;
        #pragma unroll
        for (int e = 0; e < NEXP; e++)
            if (e != i0 && r[e] > r[i1]) i1 = e;

        g_tk_e[t * 2 + 0] = i0; g_tk_w[t * 2 + 0] = r[i0];
        g_tk_e[t * 2 + 1] = i1; g_tk_w[t * 2 + 1] = r[i1];
        atomicAdd(&g_counts[i0], 1);
        atomicAdd(&g_counts[i1], 1);
    }
}

// ---------------- kernel 2: prefix -------------------------------------------
__global__ void offsets_kernel() {
    if (threadIdx.x == 0) {
        int s = 0;
        #pragma unroll
        for (int e = 0; e < NEXP; e++) { g_offsets[e] = s; s += g_counts[e]; }
    }
}

// ---------------- kernel 3: scatter -------------------------------------------
__global__ void scatter_kernel() {
    int t = blockIdx.x * blockDim.x + threadIdx.x;
    if (t >= T_TOK) return;
    #pragma unroll
    for (int k = 0; k < 2; k++) {
        int e = g_tk_e[t * 2 + k];
        int pos = atomicAdd(&g_fill[e], 1);
        int slot = g_offsets[e] + pos;
        g_slot_token[slot] = t;
        g_token_slot[t * 2 + k] = slot;
    }
}

// ======== GEMM1 fused: inter = silu(x@Wg^T) * (x@Wu^T), fp16 mma ==============
__global__ __launch_bounds__(256, 2)
void gemm1_swiglu() {
    extern __shared__ __half smh[];
    const int e = blockIdx.z;
    const int n_e = g_counts[e];
    const int m0 = blockIdx.x * BM;
    if (m0 >= n_e) return;
    const int base = g_offsets[e];
    const int n0 = blockIdx.y * BN1;

    const int tid  = threadIdx.x;
    const int warp = tid >> 5;
    const int lane = tid & 31;
    const int wm = warp & 3;
    const int wn = warp >> 2;
    const int grp = lane >> 2;
    const int t4  = lane & 3;

    float accg[2][4][4], accu[2][4][4];
    #pragma unroll
    for (int i = 0; i < 2; i++)
        #pragma unroll
        for (int j = 0; j < 4; j++)
            #pragma unroll
            for (int q = 0; q < 4; q++) { accg[i][j][q] = 0.f; accu[i][j][q] = 0.f; }

    const int lrow = tid >> 2;            // 0..63
    const int lseg = (tid & 3) * 8;       // 0,8,16,24 halfs (16B each)

    const __half* aptr[2]; int asz[2];
    #pragma unroll
    for (int h = 0; h < 2; h++) {
        int r = m0 + lrow + h * 64;
        bool v = (r < n_e);
        asz[h] = v ? 16 : 0;
        int row = v ? g_slot_token[base + r] : 0;
        aptr[h] = g_xh + (size_t)row * HID + lseg;
    }
    const __half* wbase = g_wguh + (size_t)e * GUD * HID;
    const __half* wptr[2];
    wptr[0] = wbase + (size_t)(n0 + lrow) * HID + lseg;            // gate
    wptr[1] = wbase + (size_t)(INTERD + n0 + lrow) * HID + lseg;   // up

    const int sA0 = (lrow      ) * SPADH + lseg;
    const int sA1 = (lrow +  64) * SPADH + lseg;
    const int sB0 = 128 * SPADH + (lrow      ) * SPADH + lseg;
    const int sB1 = 128 * SPADH + (lrow +  64) * SPADH + lseg;

    const int NIT = HID / BK;  // 64

    #define G1_ISSUE(it) do {                                            \
        __half* st = smh + ((it) % STAGES) * STAGE_H;                    \
        int k0 = (it) * BK;                                              \
        cp16(sptr(st + sA0), aptr[0] + k0, asz[0]);                      \
        cp16(sptr(st + sA1), aptr[1] + k0, asz[1]);                      \
        cp16(sptr(st + sB0), wptr[0] + k0, 16);                          \
        cp16(sptr(st + sB1), wptr[1] + k0, 16);                          \
    } while (0)

    G1_ISSUE(0); cp_commit();
    G1_ISSUE(1); cp_commit();
    cp_wait1();
    __syncthreads();

    for (int it = 0; it < NIT; ++it) {
        if (it + 2 < NIT) G1_ISSUE(it + 2);
        cp_commit();

        const __half* As = smh + (it % STAGES) * STAGE_H;
        const __half* Bs = As + 128 * SPADH;

        #pragma unroll
        for (int ks = 0; ks < 2; ks++) {
            const int kk = ks * 16;
            uint32_t af[2][4];
            #pragma unroll
            for (int mi = 0; mi < 2; mi++) {
                int rrow = wm * 32 + mi * 16 + grp;
                af[mi][0] = uldh(&As[(rrow    ) * SPADH + kk     + t4 * 2]);
                af[mi][1] = uldh(&As[(rrow + 8) * SPADH + kk     + t4 * 2]);
                af[mi][2] = uldh(&As[(rrow    ) * SPADH + kk + 8 + t4 * 2]);
                af[mi][3] = uldh(&As[(rrow + 8) * SPADH + kk + 8 + t4 * 2]);
            }
            uint32_t bg[4][2], bu[4][2];
            #pragma unroll
            for (int ni = 0; ni < 4; ni++) {
                int col = wn * 32 + ni * 8 + grp;
                bg[ni][0] = uldh(&Bs[(col     ) * SPADH + kk     + t4 * 2]);
                bg[ni][1] = uldh(&Bs[(col     ) * SPADH + kk + 8 + t4 * 2]);
                bu[ni][0] = uldh(&Bs[(col + 64) * SPADH + kk     + t4 * 2]);
                bu[ni][1] = uldh(&Bs[(col + 64) * SPADH + kk + 8 + t4 * 2]);
            }
            #pragma unroll
            for (int mi = 0; mi < 2; mi++)
                #pragma unroll
                for (int ni = 0; ni < 4; ni++) {
                    mma_f16(accg[mi][ni], af[mi], bg[ni]);
                    mma_f16(accu[mi][ni], af[mi], bu[ni]);
                }
        }
        cp_wait1();
        __syncthreads();
    }
    #undef G1_ISSUE

    // epilogue: silu(g)*u -> fp16 for gemm2
    #pragma unroll
    for (int mi = 0; mi < 2; mi++) {
        #pragma unroll
        for (int rh = 0; rh < 2; rh++) {
            int rloc = wm * 32 + mi * 16 + grp + rh * 8;
            int r = m0 + rloc;
            if (r >= n_e) continue;
            __half* crow = g_interh + (size_t)(base + r) * INTERD + n0;
            #pragma unroll
            for (int ni = 0; ni < 4; ni++) {
                int c = wn * 32 + ni * 8 + 2 * t4;
                float g0 = accg[mi][ni][rh * 2 + 0];
                float g1 = accg[mi][ni][rh * 2 + 1];
                float u0 = accu[mi][ni][rh * 2 + 0];
                float u1 = accu[mi][ni][rh * 2 + 1];
                float o0 = g0 / (1.f + expf(-g0)) * u0;
                float o1 = g1 / (1.f + expf(-g1)) * u1;
                *(__half2*)(crow + c) = __floats2half2_rn(o0, o1);
            }
        }
    }
}

// ======== GEMM2: south = inter @ w_down[e]^T (fp16 out) =======================
__global__ __launch_bounds__(256, 2)
void gemm2_down() {
    extern __shared__ __half smh[];
    const int e = blockIdx.z;
    const int n_e = g_counts[e];
    const int m0 = blockIdx.x * BM;
    if (m0 >= n_e) return;
    const int base = g_offsets[e];
    const int n0 = blockIdx.y * BN2;

    const int tid  = threadIdx.x;
    const int warp = tid >> 5;
    const int lane = tid & 31;
    const int wm = warp & 3;
    const int wn = warp >> 2;
    const int grp = lane >> 2;
    const int t4  = lane & 3;

    float acc[2][8][4];
    #pragma unroll
    for (int i = 0; i < 2; i++)
        #pragma unroll
        for (int j = 0; j < 8; j++)
            #pragma unroll
            for (int q = 0; q < 4; q++) acc[i][j][q] = 0.f;

    const int lrow = tid >> 2;
    const int lseg = (tid & 3) * 8;

    const __half* aptr[2]; int asz[2];
    #pragma unroll
    for (int h = 0; h < 2; h++) {
        int r = m0 + lrow + h * 64;
        bool v = (r < n_e);
        asz[h] = v ? 16 : 0;
        aptr[h] = g_interh + (size_t)(v ? (base + r) : base) * INTERD + lseg;
    }
    const __half* wptr[2];
    #pragma unroll
    for (int h = 0; h < 2; h++)
        wptr[h] = g_wdnh + (size_t)e * HID * INTERD
                + (size_t)(n0 + lrow + h * 64) * INTERD + lseg;

    const int sA0 = (lrow      ) * SPADH + lseg;
    const int sA1 = (lrow +  64) * SPADH + lseg;
    const int sB0 = 128 * SPADH + (lrow      ) * SPADH + lseg;
    const int sB1 = 128 * SPADH + (lrow +  64) * SPADH + lseg;

    const int NIT = INTERD / BK;  // 88

    #define G2_ISSUE(it) do {                                            \
        __half* st = smh + ((it) % STAGES) * STAGE_H;                    \
        int k0 = (it) * BK;                                              \
        cp16(sptr(st + sA0), aptr[0] + k0, asz[0]);                      \
        cp16(sptr(st + sA1), aptr[1] + k0, asz[1]);                      \
        cp16(sptr(st + sB0), wptr[0] + k0, 16);                          \
        cp16(sptr(st + sB1), wptr[1] + k0, 16);                          \
    } while (0)

    G2_ISSUE(0); cp_commit();
    G2_ISSUE(1); cp_commit();
    cp_wait1();
    __syncthreads();

    for (int it = 0; it < NIT; ++it) {
        if (it + 2 < NIT) G2_ISSUE(it + 2);
        cp_commit();

        const __half* As = smh + (it % STAGES) * STAGE_H;
        const __half* Bs = As + 128 * SPADH;

        #pragma unroll
        for (int ks = 0; ks < 2; ks++) {
            const int kk = ks * 16;
            uint32_t af[2][4];
            #pragma unroll
            for (int mi = 0; mi < 2; mi++) {
                int rrow = wm * 32 + mi * 16 + grp;
                af[mi][0] = uldh(&As[(rrow    ) * SPADH + kk     + t4 * 2]);
                af[mi][1] = uldh(&As[(rrow + 8) * SPADH + kk     + t4 * 2]);
                af[mi][2] = uldh(&As[(rrow    ) * SPADH + kk + 8 + t4 * 2]);
                af[mi][3] = uldh(&As[(rrow + 8) * SPADH + kk + 8 + t4 * 2]);
            }
            uint32_t bf[8][2];
            #pragma unroll
            for (int ni = 0; ni < 8; ni++) {
                int col = wn * 64 + ni * 8 + grp;
                bf[ni][0] = uldh(&Bs[col * SPADH + kk     + t4 * 2]);
                bf[ni][1] = uldh(&Bs[col * SPADH + kk + 8 + t4 * 2]);
            }
            #pragma unroll
            for (int mi = 0; mi < 2; mi++)
                #pragma unroll
                for (int ni = 0; ni < 8; ni++)
                    mma_f16(acc[mi][ni], af[mi], bf[ni]);
        }
        cp_wait1();
        __syncthreads();
    }
    #undef G2_ISSUE

    #pragma unroll
    for (int mi = 0; mi < 2; mi++) {
        #pragma unroll
        for (int rh = 0; rh < 2; rh++) {
            int rloc = wm * 32 + mi * 16 + grp + rh * 8;
            int r = m0 + rloc;
            if (r >= n_e) continue;
            __half* crow = g_south + (size_t)(base + r) * HID + n0;
            #pragma unroll
            for (int ni = 0; ni < 8; ni++) {
                int c = wn * 64 + ni * 8 + 2 * t4;
                *(__half2*)(crow + c) =
                    __floats2half2_rn(acc[mi][ni][rh * 2 + 0], acc[mi][ni][rh * 2 + 1]);
            }
        }
    }
}

// ---------------- combine (fp16 in, fp32 out) ----------------------------------
__global__ __launch_bounds__(256)
void combine_kernel(float* __restrict__ out) {
    // grid-stride over token-rows; each block handles tokens, 256 threads over 1024 half2
    const int stride = gridDim.x;
    for (int t = blockIdx.x; t < T_TOK; t += stride) {
        const int s0 = g_token_slot[t * 2 + 0];
        const int s1 = g_token_slot[t * 2 + 1];
        const float w0 = g_tk_w[t * 2 + 0];
        const float w1 = g_tk_w[t * 2 + 1];
        const __half2* a = (const __half2*)(g_south + (size_t)s0 * HID);
        const __half2* b = (const __half2*)(g_south + (size_t)s1 * HID);
        float2* o = (float2*)(out + (size_t)t * HID);
        #pragma unroll 4
        for (int i = threadIdx.x; i < HID / 2; i += 256) {
            float2 va = __half22float2(a[i]);
            float2 vb = __half22float2(b[i]);
            float2 vo;
            vo.x = w0 * va.x + w1 * vb.x;
            vo.y = w0 * va.y + w1 * vb.y;
            o[i] = vo;
        }
    }
}

// ---------------- launch ------------------------------------------------------
extern "C" void kernel_launch(void* const* d_in, const int* in_sizes, int n_in,
                              void* d_out, int out_size) {
    const float *x = 0, *gw = 0, *gb = 0, *ebias = 0, *w_gu = 0, *w_dn = 0;
    for (int i = 0; i < n_in; i++) {
        long s = in_sizes[i];
        const float* p = (const float*)d_in[i];
        if      (s == (long)T_TOK * HID)         x    = p;
        else if (s == (long)NEXP * HID)          gw   = p;
        else if (s == (long)NEXP * GUD * HID)    w_gu = p;
        else if (s == (long)NEXP * HID * INTERD) w_dn = p;
        else if (s == NEXP) { if (!gb) gb = p; else ebias = p; }
    }
    float* out = (float*)d_out;

    cudaFuncSetAttribute(gemm1_swiglu, cudaFuncAttributeMaxDynamicSharedMemorySize, SMEM_BYTES);
    cudaFuncSetAttribute(gemm2_down,   cudaFuncAttributeMaxDynamicSharedMemorySize, SMEM_BYTES);

    __half* wguh_p; cudaGetSymbolAddress((void**)&wguh_p, g_wguh);
    __half* wdnh_p; cudaGetSymbolAddress((void**)&wdnh_p, g_wdnh);

    zero_kernel<<<1, 32>>>();

    tohalf_kernel<<<1184, 256>>>((const float4*)w_gu, (uint2*)wguh_p, NEXP * GUD * HID / 4);
    tohalf_kernel<<<1184, 256>>>((const float4*)w_dn, (uint2*)wdnh_p, NEXP * HID * INTERD / 4);

    router_kernel<<<T_TOK, 128>>>(x, gw, gb, ebias);
    offsets_kernel<<<1, 32>>>();
    scatter_kernel<<<T_TOK / 256, 256>>>();

    gemm1_swiglu<<<dim3(NSLOT / BM, INTERD / BN1, NEXP), 256, SMEM_BYTES>>>();
    gemm2_down<<<dim3(NSLOT / BM, HID / BN2, NEXP), 256, SMEM_BYTES>>>();

    combine_kernel<<<2048, 256>>>(out);
}

// round 15
// speedup vs baseline: 1.0014x; 1.0014x over previous
#include <cuda_runtime.h>
#include <cuda_fp16.h>
#include <cstdint>

#define T_TOK 8192
#define HID   2048
#define NEXP  8
#define INTERD 2816
#define GUD   (2*INTERD)      // 5632
#define NSLOT (T_TOK*2)       // 16384

#define BM 128
#define BN1 64
#define BN2 128
#define BK 32                  // halfs per K-chunk (64 B rows)
#define SPADH 40               // halfs per smem row (80 B, 16B-aligned)
#define STAGES 3
#define STAGE_H (256*SPADH)    // A(128 rows) + B(128 rows) halfs per stage
#define SMEM_BYTES (STAGES*STAGE_H*2)   // 61440 B

// ---------------- scratch (static device globals; no allocation) -------------
__device__ int    g_counts[NEXP];
__device__ int    g_offsets[NEXP];
__device__ int    g_fill[NEXP];
__device__ int    g_tk_e[NSLOT];
__device__ float  g_tk_w[NSLOT];
__device__ int    g_slot_token[NSLOT];
__device__ int    g_token_slot[NSLOT];
__device__ __half g_xh  [(size_t)T_TOK * HID];         // fp16 x (34 MB)
__device__ __half g_wguh[(size_t)NEXP * GUD * HID];    // fp16 w_gate_up (185 MB)
__device__ __half g_wdnh[(size_t)NEXP * HID * INTERD]; // fp16 w_down (92 MB)
__device__ __half g_interh[(size_t)NSLOT * INTERD];    // fp16 activations (92 MB)
__device__ __half g_south[(size_t)NSLOT * HID];        // fp16 down output (67 MB)

// ---------------- helpers ----------------------------------------------------
__device__ __forceinline__ uint32_t uldh(const __half* p) {
    return *(const uint32_t*)p;
}
__device__ __forceinline__ void mma_f16(float c[4], const uint32_t a[4], const uint32_t b[2]) {
    asm volatile(
        "mma.sync.aligned.m16n8k16.row.col.f32.f16.f16.f32 "
        "{%0,%1,%2,%3}, {%4,%5,%6,%7}, {%8,%9}, {%0,%1,%2,%3};\n"
        : "+f"(c[0]), "+f"(c[1]), "+f"(c[2]), "+f"(c[3])
        : "r"(a[0]), "r"(a[1]), "r"(a[2]), "r"(a[3]), "r"(b[0]), "r"(b[1]));
}
__device__ __forceinline__ uint32_t sptr(const void* p) {
    return (uint32_t)__cvta_generic_to_shared(p);
}
__device__ __forceinline__ void cp16(uint32_t dst, const void* src, int sz) {
    asm volatile("cp.async.cg.shared.global [%0], [%1], 16, %2;\n"
                 :: "r"(dst), "l"(src), "r"(sz));
}
__device__ __forceinline__ void cp_commit() {
    asm volatile("cp.async.commit_group;\n");
}
__device__ __forceinline__ void cp_wait1() {
    asm volatile("cp.async.wait_group 1;\n");
}

// ---------------- kernel 0: zero counters ------------------------------------
__global__ void zero_kernel() {
    int i = threadIdx.x;
    if (i < NEXP) { g_counts[i] = 0; g_fill[i] = 0; }
}

// ---------------- convert: fp32 -> fp16 (weights, one-time) -------------------
__global__ __launch_bounds__(256)
void tohalf_kernel(const float4* __restrict__ in, uint2* __restrict__ out, int n4) {
    int stride = gridDim.x * blockDim.x;
    for (int i = blockIdx.x * blockDim.x + threadIdx.x; i < n4; i += stride) {
        float4 v = in[i];
        __half2 h01 = __floats2half2_rn(v.x, v.y);
        __half2 h23 = __floats2half2_rn(v.z, v.w);
        uint2 o;
        o.x = *(uint32_t*)&h01;
        o.y = *(uint32_t*)&h23;
        out[i] = o;
    }
}

// ---------------- kernel 1: router (fp32, exact) + x->fp16 fuse ---------------
__global__ __launch_bounds__(128)
void router_kernel(const float* __restrict__ x, const float* __restrict__ gw,
                   const float* __restrict__ gb, const float* __restrict__ ebias) {
    const int t = blockIdx.x;
    const float* xr = x + (size_t)t * HID;
    __half* xhr = g_xh + (size_t)t * HID;
    float acc[NEXP];
    #pragma unroll
    for (int e = 0; e < NEXP; e++) acc[e] = 0.f;

    for (int h = threadIdx.x; h < HID; h += 128) {
        float xv = xr[h];
        xhr[h] = __float2half_rn(xv);          // fused fp16 conversion
        #pragma unroll
        for (int e = 0; e < NEXP; e++) acc[e] += xv * gw[e * HID + h];
    }
    #pragma unroll
    for (int off = 16; off > 0; off >>= 1) {
        #pragma unroll
        for (int e = 0; e < NEXP; e++)
            acc[e] += __shfl_down_sync(0xffffffffu, acc[e], off);
    }
    __shared__ float ws[4][NEXP];
    int warp = threadIdx.x >> 5, lane = threadIdx.x & 31;
    if (lane == 0) {
        #pragma unroll
        for (int e = 0; e < NEXP; e++) ws[warp][e] = acc[e];
    }
    __syncthreads();
    if (threadIdx.x == 0) {
        float lg[NEXP];
        #pragma unroll
        for (int e = 0; e < NEXP; e++)
            lg[e] = ws[0][e] + ws[1][e] + ws[2][e] + ws[3][e] + gb[e];
        float m = lg[0];
        #pragma unroll
        for (int e = 1; e < NEXP; e++) m = fmaxf(m, lg[e]);
        float p[NEXP], s = 0.f;
        #pragma unroll
        for (int e = 0; e < NEXP; e++) { p[e] = expf(lg[e] - m); s += p[e]; }
        float r[NEXP];
        #pragma unroll
        for (int e = 0; e < NEXP; e++) r[e] = p[e] / s + ebias[e];
        int i0 = 0;
        #pragma unroll
        for (int e = 1; e < NEXP; e++) if (r[e] > r[i0]) i0 = e;
        int i1 = (i0 == 0) ? 1 : 0;
        #pragma unroll
        for (int e = 0; e < NEXP; e++)
            if (e != i0 && r[e] > r[i1]) i1 = e;

        g_tk_e[t * 2 + 0] = i0; g_tk_w[t * 2 + 0] = r[i0];
        g_tk_e[t * 2 + 1] = i1; g_tk_w[t * 2 + 1] = r[i1];
        atomicAdd(&g_counts[i0], 1);
        atomicAdd(&g_counts[i1], 1);
    }
}

// ---------------- kernel 2: prefix -------------------------------------------
__global__ void offsets_kernel() {
    if (threadIdx.x == 0) {
        int s = 0;
        #pragma unroll
        for (int e = 0; e < NEXP; e++) { g_offsets[e] = s; s += g_counts[e]; }
    }
}

// ---------------- kernel 3: scatter -------------------------------------------
__global__ void scatter_kernel() {
    int t = blockIdx.x * blockDim.x + threadIdx.x;
    if (t >= T_TOK) return;
    #pragma unroll
    for (int k = 0; k < 2; k++) {
        int e = g_tk_e[t * 2 + k];
        int pos = atomicAdd(&g_fill[e], 1);
        int slot = g_offsets[e] + pos;
        g_slot_token[slot] = t;
        g_token_slot[t * 2 + k] = slot;
    }
}

// ======== GEMM1 fused: inter = silu(x@Wg^T) * (x@Wu^T), fp16 mma ==============
__global__ __launch_bounds__(256, 2)
void gemm1_swiglu() {
    extern __shared__ __half smh[];
    const int e = blockIdx.z;
    const int n_e = g_counts[e];
    const int m0 = blockIdx.x * BM;
    if (m0 >= n_e) return;
    const int base = g_offsets[e];
    const int n0 = blockIdx.y * BN1;

    const int tid  = threadIdx.x;
    const int warp = tid >> 5;
    const int lane = tid & 31;
    const int wm = warp & 3;
    const int wn = warp >> 2;
    const int grp = lane >> 2;
    const int t4  = lane & 3;

    float accg[2][4][4], accu[2][4][4];
    #pragma unroll
    for (int i = 0; i < 2; i++)
        #pragma unroll
        for (int j = 0; j < 4; j++)
            #pragma unroll
            for (int q = 0; q < 4; q++) { accg[i][j][q] = 0.f; accu[i][j][q] = 0.f; }

    const int lrow = tid >> 2;            // 0..63
    const int lseg = (tid & 3) * 8;       // 0,8,16,24 halfs (16B each)

    const __half* aptr[2]; int asz[2];
    #pragma unroll
    for (int h = 0; h < 2; h++) {
        int r = m0 + lrow + h * 64;
        bool v = (r < n_e);
        asz[h] = v ? 16 : 0;
        int row = v ? g_slot_token[base + r] : 0;
        aptr[h] = g_xh + (size_t)row * HID + lseg;
    }
    const __half* wbase = g_wguh + (size_t)e * GUD * HID;
    const __half* wptr[2];
    wptr[0] = wbase + (size_t)(n0 + lrow) * HID + lseg;            // gate
    wptr[1] = wbase + (size_t)(INTERD + n0 + lrow) * HID + lseg;   // up

    const int sA0 = (lrow      ) * SPADH + lseg;
    const int sA1 = (lrow +  64) * SPADH + lseg;
    const int sB0 = 128 * SPADH + (lrow      ) * SPADH + lseg;
    const int sB1 = 128 * SPADH + (lrow +  64) * SPADH + lseg;

    const int NIT = HID / BK;  // 64

    #define G1_ISSUE(it) do {                                            \
        __half* st = smh + ((it) % STAGES) * STAGE_H;                    \
        int k0 = (it) * BK;                                              \
        cp16(sptr(st + sA0), aptr[0] + k0, asz[0]);                      \
        cp16(sptr(st + sA1), aptr[1] + k0, asz[1]);                      \
        cp16(sptr(st + sB0), wptr[0] + k0, 16);                          \
        cp16(sptr(st + sB1), wptr[1] + k0, 16);                          \
    } while (0)

    G1_ISSUE(0); cp_commit();
    G1_ISSUE(1); cp_commit();
    cp_wait1();
    __syncthreads();

    for (int it = 0; it < NIT; ++it) {
        if (it + 2 < NIT) G1_ISSUE(it + 2);
        cp_commit();

        const __half* As = smh + (it % STAGES) * STAGE_H;
        const __half* Bs = As + 128 * SPADH;

        #pragma unroll
        for (int ks = 0; ks < 2; ks++) {
            const int kk = ks * 16;
            uint32_t af[2][4];
            #pragma unroll
            for (int mi = 0; mi < 2; mi++) {
                int rrow = wm * 32 + mi * 16 + grp;
                af[mi][0] = uldh(&As[(rrow    ) * SPADH + kk     + t4 * 2]);
                af[mi][1] = uldh(&As[(rrow + 8) * SPADH + kk     + t4 * 2]);
                af[mi][2] = uldh(&As[(rrow    ) * SPADH + kk + 8 + t4 * 2]);
                af[mi][3] = uldh(&As[(rrow + 8) * SPADH + kk + 8 + t4 * 2]);
            }
            uint32_t bg[4][2], bu[4][2];
            #pragma unroll
            for (int ni = 0; ni < 4; ni++) {
                int col = wn * 32 + ni * 8 + grp;
                bg[ni][0] = uldh(&Bs[(col     ) * SPADH + kk     + t4 * 2]);
                bg[ni][1] = uldh(&Bs[(col     ) * SPADH + kk + 8 + t4 * 2]);
                bu[ni][0] = uldh(&Bs[(col + 64) * SPADH + kk     + t4 * 2]);
                bu[ni][1] = uldh(&Bs[(col + 64) * SPADH + kk + 8 + t4 * 2]);
            }
            #pragma unroll
            for (int mi = 0; mi < 2; mi++)
                #pragma unroll
                for (int ni = 0; ni < 4; ni++) {
                    mma_f16(accg[mi][ni], af[mi], bg[ni]);
                    mma_f16(accu[mi][ni], af[mi], bu[ni]);
                }
        }
        cp_wait1();
        __syncthreads();
    }
    #undef G1_ISSUE

    // epilogue: silu(g)*u -> fp16 for gemm2
    #pragma unroll
    for (int mi = 0; mi < 2; mi++) {
        #pragma unroll
        for (int rh = 0; rh < 2; rh++) {
            int rloc = wm * 32 + mi * 16 + grp + rh * 8;
            int r = m0 + rloc;
            if (r >= n_e) continue;
            __half* crow = g_interh + (size_t)(base + r) * INTERD + n0;
            #pragma unroll
            for (int ni = 0; ni < 4; ni++) {
                int c = wn * 32 + ni * 8 + 2 * t4;
                float g0 = accg[mi][ni][rh * 2 + 0];
                float g1 = accg[mi][ni][rh * 2 + 1];
                float u0 = accu[mi][ni][rh * 2 + 0];
                float u1 = accu[mi][ni][rh * 2 + 1];
                float o0 = g0 / (1.f + expf(-g0)) * u0;
                float o1 = g1 / (1.f + expf(-g1)) * u1;
                *(__half2*)(crow + c) = __floats2half2_rn(o0, o1);
            }
        }
    }
}

// ======== GEMM2: south = inter @ w_down[e]^T (fp16 out) =======================
__global__ __launch_bounds__(256, 2)
void gemm2_down() {
    extern __shared__ __half smh[];
    const int e = blockIdx.z;
    const int n_e = g_counts[e];
    const int m0 = blockIdx.x * BM;
    if (m0 >= n_e) return;
    const int base = g_offsets[e];
    const int n0 = blockIdx.y * BN2;

    const int tid  = threadIdx.x;
    const int warp = tid >> 5;
    const int lane = tid & 31;
    const int wm = warp & 3;
    const int wn = warp >> 2;
    const int grp = lane >> 2;
    const int t4  = lane & 3;

    float acc[2][8][4];
    #pragma unroll
    for (int i = 0; i < 2; i++)
        #pragma unroll
        for (int j = 0; j < 8; j++)
            #pragma unroll
            for (int q = 0; q < 4; q++) acc[i][j][q] = 0.f;

    const int lrow = tid >> 2;
    const int lseg = (tid & 3) * 8;

    const __half* aptr[2]; int asz[2];
    #pragma unroll
    for (int h = 0; h < 2; h++) {
        int r = m0 + lrow + h * 64;
        bool v = (r < n_e);
        asz[h] = v ? 16 : 0;
        aptr[h] = g_interh + (size_t)(v ? (base + r) : base) * INTERD + lseg;
    }
    const __half* wptr[2];
    #pragma unroll
    for (int h = 0; h < 2; h++)
        wptr[h] = g_wdnh + (size_t)e * HID * INTERD
                + (size_t)(n0 + lrow + h * 64) * INTERD + lseg;

    const int sA0 = (lrow      ) * SPADH + lseg;
    const int sA1 = (lrow +  64) * SPADH + lseg;
    const int sB0 = 128 * SPADH + (lrow      ) * SPADH + lseg;
    const int sB1 = 128 * SPADH + (lrow +  64) * SPADH + lseg;

    const int NIT = INTERD / BK;  // 88

    #define G2_ISSUE(it) do {                                            \
        __half* st = smh + ((it) % STAGES) * STAGE_H;                    \
        int k0 = (it) * BK;                                              \
        cp16(sptr(st + sA0), aptr[0] + k0, asz[0]);                      \
        cp16(sptr(st + sA1), aptr[1] + k0, asz[1]);                      \
        cp16(sptr(st + sB0), wptr[0] + k0, 16);                          \
        cp16(sptr(st + sB1), wptr[1] + k0, 16);                          \
    } while (0)

    G2_ISSUE(0); cp_commit();
    G2_ISSUE(1); cp_commit();
    cp_wait1();
    __syncthreads();

    for (int it = 0; it < NIT; ++it) {
        if (it + 2 < NIT) G2_ISSUE(it + 2);
        cp_commit();

        const __half* As = smh + (it % STAGES) * STAGE_H;
        const __half* Bs = As + 128 * SPADH;

        #pragma unroll
        for (int ks = 0; ks < 2; ks++) {
            const int kk = ks * 16;
            uint32_t af[2][4];
            #pragma unroll
            for (int mi = 0; mi < 2; mi++) {
                int rrow = wm * 32 + mi * 16 + grp;
                af[mi][0] = uldh(&As[(rrow    ) * SPADH + kk     + t4 * 2]);
                af[mi][1] = uldh(&As[(rrow + 8) * SPADH + kk     + t4 * 2]);
                af[mi][2] = uldh(&As[(rrow    ) * SPADH + kk + 8 + t4 * 2]);
                af[mi][3] = uldh(&As[(rrow + 8) * SPADH + kk + 8 + t4 * 2]);
            }
            uint32_t bf[8][2];
            #pragma unroll
            for (int ni = 0; ni < 8; ni++) {
                int col = wn * 64 + ni * 8 + grp;
                bf[ni][0] = uldh(&Bs[col * SPADH + kk     + t4 * 2]);
                bf[ni][1] = uldh(&Bs[col * SPADH + kk + 8 + t4 * 2]);
            }
            #pragma unroll
            for (int mi = 0; mi < 2; mi++)
                #pragma unroll
                for (int ni = 0; ni < 8; ni++)
                    mma_f16(acc[mi][ni], af[mi], bf[ni]);
        }
        cp_wait1();
        __syncthreads();
    }
    #undef G2_ISSUE

    #pragma unroll
    for (int mi = 0; mi < 2; mi++) {
        #pragma unroll
        for (int rh = 0; rh < 2; rh++) {
            int rloc = wm * 32 + mi * 16 + grp + rh * 8;
            int r = m0 + rloc;
            if (r >= n_e) continue;
            __half* crow = g_south + (size_t)(base + r) * HID + n0;
            #pragma unroll
            for (int ni = 0; ni < 8; ni++) {
                int c = wn * 64 + ni * 8 + 2 * t4;
                *(__half2*)(crow + c) =
                    __floats2half2_rn(acc[mi][ni][rh * 2 + 0], acc[mi][ni][rh * 2 + 1]);
            }
        }
    }
}

// ---------------- combine (fp16 in, fp32 out) ----------------------------------
__global__ __launch_bounds__(256)
void combine_kernel(float* __restrict__ out) {
    // grid-stride over token-rows; each block handles tokens, 256 threads over 1024 half2
    const int stride = gridDim.x;
    for (int t = blockIdx.x; t < T_TOK; t += stride) {
        const int s0 = g_token_slot[t * 2 + 0];
        const int s1 = g_token_slot[t * 2 + 1];
        const float w0 = g_tk_w[t * 2 + 0];
        const float w1 = g_tk_w[t * 2 + 1];
        const __half2* a = (const __half2*)(g_south + (size_t)s0 * HID);
        const __half2* b = (const __half2*)(g_south + (size_t)s1 * HID);
        float2* o = (float2*)(out + (size_t)t * HID);
        #pragma unroll 4
        for (int i = threadIdx.x; i < HID / 2; i += 256) {
            float2 va = __half22float2(a[i]);
            float2 vb = __half22float2(b[i]);
            float2 vo;
            vo.x = w0 * va.x + w1 * vb.x;
            vo.y = w0 * va.y + w1 * vb.y;
            o[i] = vo;
        }
    }
}

// ---------------- launch ------------------------------------------------------
extern "C" void kernel_launch(void* const* d_in, const int* in_sizes, int n_in,
                              void* d_out, int out_size) {
    const float *x = 0, *gw = 0, *gb = 0, *ebias = 0, *w_gu = 0, *w_dn = 0;
    for (int i = 0; i < n_in; i++) {
        long s = in_sizes[i];
        const float* p = (const float*)d_in[i];
        if      (s == (long)T_TOK * HID)         x    = p;
        else if (s == (long)NEXP * HID)          gw   = p;
        else if (s == (long)NEXP * GUD * HID)    w_gu = p;
        else if (s == (long)NEXP * HID * INTERD) w_dn = p;
        else if (s == NEXP) { if (!gb) gb = p; else ebias = p; }
    }
    float* out = (float*)d_out;

    cudaFuncSetAttribute(gemm1_swiglu, cudaFuncAttributeMaxDynamicSharedMemorySize, SMEM_BYTES);
    cudaFuncSetAttribute(gemm2_down,   cudaFuncAttributeMaxDynamicSharedMemorySize, SMEM_BYTES);

    __half* wguh_p; cudaGetSymbolAddress((void**)&wguh_p, g_wguh);
    __half* wdnh_p; cudaGetSymbolAddress((void**)&wdnh_p, g_wdnh);

    zero_kernel<<<1, 32>>>();

    tohalf_kernel<<<1184, 256>>>((const float4*)w_gu, (uint2*)wguh_p, NEXP * GUD * HID / 4);
    tohalf_kernel<<<1184, 256>>>((const float4*)w_dn, (uint2*)wdnh_p, NEXP * HID * INTERD / 4);

    router_kernel<<<T_TOK, 128>>>(x, gw, gb, ebias);
    offsets_kernel<<<1, 32>>>();
    scatter_kernel<<<T_TOK / 256, 256>>>();

    gemm1_swiglu<<<dim3(NSLOT / BM, INTERD / BN1, NEXP), 256, SMEM_BYTES>>>();
    gemm2_down<<<dim3(NSLOT / BM, HID / BN2, NEXP), 256, SMEM_BYTES>>>();

    combine_kernel<<<2048, 256>>>(out);
}